// round 16
// baseline (speedup 1.0000x reference)
#include <cuda_runtime.h>
#include <cuda_fp16.h>

// L1OrderLoss (Chamfer-style L1, PTS_DIM=2): pred/target [8192,128] f32.
// Per row (64 2-D points): dist_1[i,c]=min_j|p[i,c]-t[j,c]|, dist_2[j,c]=min_i|.|
// out = 0.5*(sum d1 + sum d2) / (N*P*2) / 64
//
// R16 = R14 per-warp body VERBATIM (f16x2 engine, 8 half2 accumulators,
// __habs2 fused into HMNMX|src|), but 256-thread blocks (8 rows/block),
// grid 1024: half the blocks -> half the scheduling/ramp/drain overhead
// that has been pinning achieved occupancy at ~53%.

#define NROWS   8192
#define PPTS    64
#define RPB     8                      // rows (warps) per block
#define THREADS (RPB * 32)             // 256
#define GRID    (NROWS / RPB)          // 1024

#define OUT_SCALE (0.5f / (8192.0f * 128.0f * 64.0f))

// Cross-launch accumulator state; last block resets -> replay-idempotent.
__device__ float        g_acc = 0.0f;
__device__ unsigned int g_cnt = 0u;

__device__ __forceinline__ __half2 u2h(unsigned int u) {
    return *reinterpret_cast<__half2*>(&u);
}
__device__ __forceinline__ unsigned int h2u(__half2 h) {
    return *reinterpret_cast<unsigned int*>(&h);
}

__global__ __launch_bounds__(THREADS, 8)
void l1order_kernel(const float* __restrict__ pred,
                    const float* __restrict__ target,
                    float* __restrict__ out)
{
    __shared__ __align__(16) __half2 psh[RPB][PPTS];   // pred points (half2)
    __shared__ __align__(16) __half2 tsh[RPB][PPTS];   // target points (half2)
    __shared__ float warp_sums[RPB];

    const int tid = threadIdx.x;
    const int w   = tid >> 5;        // warp = local row
    const int l   = tid & 31;        // lane; owns points 2l, 2l+1
    const int row = blockIdx.x * RPB + w;

    // Lane loads its 2 points of each array (float4 = 2 points, coalesced).
    const float4* predv4   = reinterpret_cast<const float4*>(pred);
    const float4* targetv4 = reinterpret_cast<const float4*>(target);
    float4 P = predv4[row * 32 + l];
    float4 T = targetv4[row * 32 + l];

    __half2 hp0 = __floats2half2_rn(P.x, P.y);
    __half2 hp1 = __floats2half2_rn(P.z, P.w);
    __half2 ht0 = __floats2half2_rn(T.x, T.y);
    __half2 ht1 = __floats2half2_rn(T.z, T.w);

    // Store both points with one STS.64 per array.
    *reinterpret_cast<uint2*>(&psh[w][2 * l]) = make_uint2(h2u(hp0), h2u(hp1));
    *reinterpret_cast<uint2*>(&tsh[w][2 * l]) = make_uint2(h2u(ht0), h2u(ht1));

    __syncwarp();

    const __half2 HBIG = __float2half2_rn(60000.0f);
    // d1 accumulators for own preds p0,p1; d2 for own targets t0,t1 (a/b split).
    __half2 a10 = HBIG, b10 = HBIG, a11 = HBIG, b11 = HBIG;
    __half2 a20 = HBIG, b20 = HBIG, a21 = HBIG, b21 = HBIG;

    const uint4* tv4 = reinterpret_cast<const uint4*>(&tsh[w][0]);  // 16 x uint4
    const uint4* pv4 = reinterpret_cast<const uint4*>(&psh[w][0]);

    // Visiting target point ht -> d1 updates for own preds (sets A=even, B=odd).
#define D1(ht, A10, A11)                                              \
    do {                                                              \
        __half2 _h = (ht);                                            \
        A10 = __hmin2(A10, __habs2(__hsub2(hp0, _h)));                \
        A11 = __hmin2(A11, __habs2(__hsub2(hp1, _h)));                \
    } while (0)
    // Visiting pred point hq -> d2 updates for own targets.
#define D2(hq, A20, A21)                                              \
    do {                                                              \
        __half2 _h = (hq);                                            \
        A20 = __hmin2(A20, __habs2(__hsub2(_h, ht0)));                \
        A21 = __hmin2(A21, __habs2(__hsub2(_h, ht1)));                \
    } while (0)

    #pragma unroll 4
    for (int c = 0; c < 8; ++c) {
        // 8 visiting targets + 8 visiting preds per iteration (4 LDS.128).
        uint4 T0 = tv4[2 * c];
        uint4 T1 = tv4[2 * c + 1];
        uint4 P0 = pv4[2 * c];
        uint4 P1 = pv4[2 * c + 1];

        D1(u2h(T0.x), a10, a11);  D1(u2h(T0.y), b10, b11);
        D1(u2h(T0.z), a10, a11);  D1(u2h(T0.w), b10, b11);
        D1(u2h(T1.x), a10, a11);  D1(u2h(T1.y), b10, b11);
        D1(u2h(T1.z), a10, a11);  D1(u2h(T1.w), b10, b11);

        D2(u2h(P0.x), a20, a21);  D2(u2h(P0.y), b20, b21);
        D2(u2h(P0.z), a20, a21);  D2(u2h(P0.w), b20, b21);
        D2(u2h(P1.x), a20, a21);  D2(u2h(P1.y), b20, b21);
        D2(u2h(P1.z), a20, a21);  D2(u2h(P1.w), b20, b21);
    }
#undef D1
#undef D2

    // Combine a/b, convert to f32, sum both coords of all 4 mins.
    float2 f0 = __half22float2(__hmin2(a10, b10));
    float2 f1 = __half22float2(__hmin2(a11, b11));
    float2 f2 = __half22float2(__hmin2(a20, b20));
    float2 f3 = __half22float2(__hmin2(a21, b21));
    float s = ((f0.x + f0.y) + (f1.x + f1.y))
            + ((f2.x + f2.y) + (f3.x + f3.y));

    #pragma unroll
    for (int off = 16; off > 0; off >>= 1)
        s += __shfl_down_sync(0xFFFFFFFFu, s, off);

    if (l == 0) warp_sums[w] = s;
    __syncthreads();

    if (tid == 0) {
        float v = ((warp_sums[0] + warp_sums[1]) + (warp_sums[2] + warp_sums[3]))
                + ((warp_sums[4] + warp_sums[5]) + (warp_sums[6] + warp_sums[7]));
        atomicAdd(&g_acc, v * OUT_SCALE);
        __threadfence();
        unsigned int done = atomicAdd(&g_cnt, 1u);
        if (done == GRID - 1u) {
            out[0] = g_acc;               // all adds visible (fence-before-count)
            g_acc = 0.0f;
            __threadfence();
            g_cnt = 0u;
        }
    }
}

extern "C" void kernel_launch(void* const* d_in, const int* in_sizes, int n_in,
                              void* d_out, int out_size)
{
    const float* pred   = (const float*)d_in[0];
    const float* target = (const float*)d_in[1];
    float* out = (float*)d_out;

    l1order_kernel<<<GRID, THREADS>>>(pred, target, out);
}

// round 17
// speedup vs baseline: 1.0400x; 1.0400x over previous
#include <cuda_runtime.h>
#include <cuda_fp16.h>

// L1OrderLoss (Chamfer-style L1, PTS_DIM=2): pred/target [8192,128] f32.
// Per row (64 2-D points): dist_1[i,c]=min_j|p[i,c]-t[j,c]|, dist_2[j,c]=min_i|.|
// out = 0.5*(sum d1 + sum d2) / (N*P*2) / 64
//
// R17 = R14 f16x2 per-row engine, but each warp processes 2 ROWS sequentially
// (rows bid*4+w and bid*4+w+4096): halves CTA count and the completion-spread
// drain tail that has pinned achieved occupancy at ~53% across all configs.

#define NROWS   8192
#define PPTS    64
#define RPB     4                      // rows (warps) per block per iteration
#define THREADS (RPB * 32)             // 128
#define GRID    1024                   // 2 iterations x 1024 x 4 rows = 8192
#define ROW_STRIDE (GRID * RPB)        // 4096

#define OUT_SCALE (0.5f / (8192.0f * 128.0f * 64.0f))

// Cross-launch accumulator state; last block resets -> replay-idempotent.
__device__ float        g_acc = 0.0f;
__device__ unsigned int g_cnt = 0u;

__device__ __forceinline__ __half2 u2h(unsigned int u) {
    return *reinterpret_cast<__half2*>(&u);
}
__device__ __forceinline__ unsigned int h2u(__half2 h) {
    return *reinterpret_cast<unsigned int*>(&h);
}

__global__ __launch_bounds__(THREADS, 13)
void l1order_kernel(const float* __restrict__ pred,
                    const float* __restrict__ target,
                    float* __restrict__ out)
{
    __shared__ __align__(16) __half2 psh[RPB][PPTS];   // pred points (half2)
    __shared__ __align__(16) __half2 tsh[RPB][PPTS];   // target points (half2)
    __shared__ float warp_sums[RPB];

    const int tid = threadIdx.x;
    const int w   = tid >> 5;        // warp = local row slot
    const int l   = tid & 31;        // lane; owns points 2l, 2l+1

    const float4* predv4   = reinterpret_cast<const float4*>(pred);
    const float4* targetv4 = reinterpret_cast<const float4*>(target);

    const uint4* tv4 = reinterpret_cast<const uint4*>(&tsh[w][0]);  // 16 x uint4
    const uint4* pv4 = reinterpret_cast<const uint4*>(&psh[w][0]);

    float s_total = 0.0f;

    #pragma unroll
    for (int it = 0; it < 2; ++it) {
        const int row = it * ROW_STRIDE + blockIdx.x * RPB + w;

        // Lane loads its 2 points of each array (float4 = 2 points, coalesced).
        float4 P = predv4[row * 32 + l];
        float4 T = targetv4[row * 32 + l];

        __half2 hp0 = __floats2half2_rn(P.x, P.y);
        __half2 hp1 = __floats2half2_rn(P.z, P.w);
        __half2 ht0 = __floats2half2_rn(T.x, T.y);
        __half2 ht1 = __floats2half2_rn(T.z, T.w);

        // Store both points with one STS.64 per array.
        *reinterpret_cast<uint2*>(&psh[w][2 * l]) = make_uint2(h2u(hp0), h2u(hp1));
        *reinterpret_cast<uint2*>(&tsh[w][2 * l]) = make_uint2(h2u(ht0), h2u(ht1));

        __syncwarp();

        const __half2 HBIG = __float2half2_rn(60000.0f);
        // d1 accumulators for own preds p0,p1; d2 for own targets t0,t1 (a/b).
        __half2 a10 = HBIG, b10 = HBIG, a11 = HBIG, b11 = HBIG;
        __half2 a20 = HBIG, b20 = HBIG, a21 = HBIG, b21 = HBIG;

        // Visiting target ht -> d1 updates; visiting pred hq -> d2 updates.
#define D1(ht, A10, A11)                                              \
        do {                                                          \
            __half2 _h = (ht);                                        \
            A10 = __hmin2(A10, __habs2(__hsub2(hp0, _h)));            \
            A11 = __hmin2(A11, __habs2(__hsub2(hp1, _h)));            \
        } while (0)
#define D2(hq, A20, A21)                                              \
        do {                                                          \
            __half2 _h = (hq);                                        \
            A20 = __hmin2(A20, __habs2(__hsub2(_h, ht0)));            \
            A21 = __hmin2(A21, __habs2(__hsub2(_h, ht1)));            \
        } while (0)

        #pragma unroll 4
        for (int c = 0; c < 8; ++c) {
            uint4 T0 = tv4[2 * c];
            uint4 T1 = tv4[2 * c + 1];
            uint4 P0 = pv4[2 * c];
            uint4 P1 = pv4[2 * c + 1];

            D1(u2h(T0.x), a10, a11);  D1(u2h(T0.y), b10, b11);
            D1(u2h(T0.z), a10, a11);  D1(u2h(T0.w), b10, b11);
            D1(u2h(T1.x), a10, a11);  D1(u2h(T1.y), b10, b11);
            D1(u2h(T1.z), a10, a11);  D1(u2h(T1.w), b10, b11);

            D2(u2h(P0.x), a20, a21);  D2(u2h(P0.y), b20, b21);
            D2(u2h(P0.z), a20, a21);  D2(u2h(P0.w), b20, b21);
            D2(u2h(P1.x), a20, a21);  D2(u2h(P1.y), b20, b21);
            D2(u2h(P1.z), a20, a21);  D2(u2h(P1.w), b20, b21);
        }
#undef D1
#undef D2

        float2 f0 = __half22float2(__hmin2(a10, b10));
        float2 f1 = __half22float2(__hmin2(a11, b11));
        float2 f2 = __half22float2(__hmin2(a20, b20));
        float2 f3 = __half22float2(__hmin2(a21, b21));
        s_total += ((f0.x + f0.y) + (f1.x + f1.y))
                 + ((f2.x + f2.y) + (f3.x + f3.y));

        __syncwarp();   // all reads of the tiles done before next overwrite
    }

    #pragma unroll
    for (int off = 16; off > 0; off >>= 1)
        s_total += __shfl_down_sync(0xFFFFFFFFu, s_total, off);

    if (l == 0) warp_sums[w] = s_total;
    __syncthreads();

    if (tid == 0) {
        float v = (warp_sums[0] + warp_sums[1]) + (warp_sums[2] + warp_sums[3]);
        atomicAdd(&g_acc, v * OUT_SCALE);
        __threadfence();
        unsigned int done = atomicAdd(&g_cnt, 1u);
        if (done == GRID - 1u) {
            out[0] = g_acc;               // all adds visible (fence-before-count)
            g_acc = 0.0f;
            __threadfence();
            g_cnt = 0u;
        }
    }
}

extern "C" void kernel_launch(void* const* d_in, const int* in_sizes, int n_in,
                              void* d_out, int out_size)
{
    const float* pred   = (const float*)d_in[0];
    const float* target = (const float*)d_in[1];
    float* out = (float*)d_out;

    l1order_kernel<<<GRID, THREADS>>>(pred, target, out);
}